// round 3
// baseline (speedup 1.0000x reference)
#include <cuda_runtime.h>
#include <cstdint>

// Spatial RNN, 4 directions, R=8 chain steps, C=64 channels.
// x: (8,192,192,64) fp32; W_*: (64,64); out: (8,192,192,256)
//
// R3: quarter-split lines with 8-row halos. CTA = (line, quarter): computes
// state on a 64-row region, outputs 48 valid rows. 2 dirs x 8 chained
// [64,64]x[64,64] GEMM steps via mma.sync tf32. B fragments in registers,
// A from smem ping-pong (permuted layout, conflict-free LDS.64).
// smem 56 KB -> 2 CTAs/SM (16 warps) for latency hiding.

#define LSTR 72                 // floats; word stride 36 = 4 mod 32 -> A LDS.64 conflict-free
#define BROWS 66                // 64 region rows + guard row each side
#define BUFSZ (BROWS * LSTR)    // 4752 floats
#define WSTR 72
#define WBUF (64 * WSTR)        // 4608 floats
#define SMEM_BYTES ((2 * BUFSZ + WBUF) * 4)   // 56448
#define NLINES_H 1536

__device__ __forceinline__ float tf32r(float v) {
    float r;
    asm("cvt.rna.tf32.f32 %0, %1;" : "=f"(r) : "f"(v));
    return r;
}

// column permutation: cols c and c+4 adjacent within each 8-col group
__device__ __forceinline__ int slotc(int c) {
    return ((c >> 3) << 3) + ((c & 3) << 1) + ((c & 7) >> 2);
}

__device__ __forceinline__ void mma_tf32(float c[4], const float a[4], const float b[2]) {
    const uint32_t* A = reinterpret_cast<const uint32_t*>(a);
    const uint32_t* B = reinterpret_cast<const uint32_t*>(b);
    asm volatile(
        "mma.sync.aligned.m16n8k8.row.col.f32.tf32.tf32.f32 "
        "{%0,%1,%2,%3}, {%4,%5,%6,%7}, {%8,%9}, {%0,%1,%2,%3};"
        : "+f"(c[0]), "+f"(c[1]), "+f"(c[2]), "+f"(c[3])
        : "r"(A[0]), "r"(A[1]), "r"(A[2]), "r"(A[3]), "r"(B[0]), "r"(B[1]));
}

extern "C" __global__ void __launch_bounds__(256, 2)
rnn_kernel(const float* __restrict__ x,
           const float* __restrict__ W_left, const float* __restrict__ W_right,
           const float* __restrict__ W_up,   const float* __restrict__ W_down,
           float* __restrict__ out)
{
    extern __shared__ float smem[];
    float* P0 = smem;               // ping-pong state (tf32-rounded, permuted)
    float* P1 = P0 + BUFSZ;
    float* Wb = P1 + BUFSZ;         // raw W staging [64][72]

    const int tid  = threadIdx.x;
    const int lane = tid & 31;
    const int warp = tid >> 5;
    const int mg   = warp & 3;      // 4 m-groups of 16 rows
    const int ng   = warp >> 2;     // 2 n-groups of 32 cols
    const int gID  = lane >> 2;     // 0..7
    const int tg   = lane & 3;      // 0..3
    const int s0_  = ((2 * tg) & 3) * 2 + ((2 * tg) >> 2);         // {0,4,1,5}
    const int s1_  = ((2 * tg + 1) & 3) * 2 + ((2 * tg + 1) >> 2); // {2,6,3,7}

    long inBase, outBase;
    int pixIn, pixOut, chBase;
    const float *Wfp, *Wbp;
    {
        int l = blockIdx.x;
        if (l < NLINES_H) {                      // horizontal row
            inBase  = (long)l * (192 * 64);
            outBase = (long)l * (192 * 256);
            pixIn   = 64;   pixOut = 256;  chBase = 0;
            Wfp = W_left;  Wbp = W_right;
        } else {                                  // vertical column
            int l2 = l - NLINES_H;
            int b = l2 / 192, w = l2 % 192;
            inBase  = (long)b * (192 * 192 * 64)  + (long)w * 64;
            outBase = (long)b * (192 * 192 * 256) + (long)w * 256;
            pixIn   = 192 * 64;  pixOut = 192 * 256;  chBase = 128;
            Wfp = W_up;  Wbp = W_down;
        }
    }
    const float* xl = x + inBase;
    float* ol = out + outBase;

    const int q  = blockIdx.y;        // quarter 0..3
    const int g0 = q * 48 - 8;        // global row of buffer row 1

    // zero guard rows (rows 0 and 65) once
    if (tid < LSTR) {
        P0[tid] = 0.f;  P0[65 * LSTR + tid] = 0.f;
        P1[tid] = 0.f;  P1[65 * LSTR + tid] = 0.f;
    }

    const int m0 = mg * 16;
    const int n0 = ng * 32;
    const int xr  = tid >> 2;          // 0..63: region row / W row
    const int xc0 = (tid & 3) * 16;    // col base

    #pragma unroll 1
    for (int dir = 0; dir < 2; dir++) {
        const float* Wg  = dir ? Wbp : Wfp;
        const int shift  = dir ? 1 : -1;     // fwd reads r-1, bwd reads r+1

        __syncthreads();   // previous dir's smem reads complete

        // ---- load x region into P0 (tf32-rounded, permuted), W into Wb (raw) ----
        {
            int grow = g0 + xr;
            bool valid = (unsigned)grow < 192u;
            const float* xp = xl + (long)grow * pixIn + xc0;
            float* row = &P0[(xr + 1) * LSTR];
            #pragma unroll
            for (int j = 0; j < 4; j++) {
                float4 v = valid ? *reinterpret_cast<const float4*>(xp + j * 4)
                                 : make_float4(0.f, 0.f, 0.f, 0.f);
                int c = xc0 + j * 4;
                row[slotc(c)]     = tf32r(v.x);
                row[slotc(c + 1)] = tf32r(v.y);
                row[slotc(c + 2)] = tf32r(v.z);
                row[slotc(c + 3)] = tf32r(v.w);
            }
            const float* wp = Wg + xr * 64 + xc0;
            float* wrow = &Wb[xr * WSTR + xc0];
            #pragma unroll
            for (int j = 0; j < 4; j++)
                *reinterpret_cast<float4*>(wrow + j * 4) =
                    *reinterpret_cast<const float4*>(wp + j * 4);
        }
        __syncthreads();

        // ---- B fragments to registers (tf32-rounded), conflict-free LDS ----
        float b[8][4][2];
        #pragma unroll
        for (int kc = 0; kc < 8; kc++)
            #pragma unroll
            for (int nt = 0; nt < 4; nt++) {
                int nn = n0 + nt * 8 + gID;
                b[kc][nt][0] = tf32r(Wb[(kc * 8 + tg) * WSTR + nn]);
                b[kc][nt][1] = tf32r(Wb[(kc * 8 + tg + 4) * WSTR + nn]);
            }

        float acc[4][4];
        #pragma unroll
        for (int nt = 0; nt < 4; nt++)
            #pragma unroll
            for (int e = 0; e < 4; e++) acc[nt][e] = 0.f;

        const int offA = (m0 + gID + shift + 1) * LSTR + 2 * tg;
        const int offS = (m0 + gID + 1) * LSTR + n0;

        const float* src = P0;
        float* dst = P1;

        #pragma unroll 1
        for (int s = 0; s < 8; s++) {
            float Cf[4][4];
            #pragma unroll
            for (int nt = 0; nt < 4; nt++)
                #pragma unroll
                for (int e = 0; e < 4; e++) Cf[nt][e] = 0.f;

            #pragma unroll
            for (int kc = 0; kc < 8; kc++) {
                float2 lo = *reinterpret_cast<const float2*>(&src[offA + kc * 8]);
                float2 hi = *reinterpret_cast<const float2*>(&src[offA + 8 * LSTR + kc * 8]);
                float a[4] = { lo.x, hi.x, lo.y, hi.y };
                #pragma unroll
                for (int nt = 0; nt < 4; nt++)
                    mma_tf32(Cf[nt], a, b[kc][nt]);
            }

            const bool last = (s == 7);
            #pragma unroll
            for (int nt = 0; nt < 4; nt++) {
                float v0 = tf32r(fmaxf(Cf[nt][0], 0.f));
                float v1 = tf32r(fmaxf(Cf[nt][1], 0.f));
                float v2 = tf32r(fmaxf(Cf[nt][2], 0.f));
                float v3 = tf32r(fmaxf(Cf[nt][3], 0.f));
                acc[nt][0] += v0;  acc[nt][1] += v1;
                acc[nt][2] += v2;  acc[nt][3] += v3;
                if (!last) {
                    float* d = &dst[offS + nt * 8];
                    d[s0_]            = v0;
                    d[s1_]            = v1;
                    d[8 * LSTR + s0_] = v2;
                    d[8 * LSTR + s1_] = v3;
                }
            }

            if (!last) __syncthreads();
            const float* t = src; src = dst; dst = const_cast<float*>(t);
        }

        // ---- epilogue: out = x + acc for valid rows (buffer rows 9..56) ----
        const int cb  = chBase + dir * 64;
        const int br0 = m0 + gID + 1;
        #pragma unroll
        for (int h = 0; h < 2; h++) {
            int br = br0 + h * 8;
            if (br >= 9 && br < 57) {
                int grow = g0 + br - 1;
                #pragma unroll
                for (int nt = 0; nt < 4; nt++) {
                    int col = n0 + nt * 8 + 2 * tg;
                    float2 xv = *reinterpret_cast<const float2*>(
                        xl + (long)grow * pixIn + col);
                    float2 o = make_float2(xv.x + acc[nt][2 * h],
                                           xv.y + acc[nt][2 * h + 1]);
                    *reinterpret_cast<float2*>(
                        ol + (long)grow * pixOut + cb + col) = o;
                }
            }
        }
    }
}

extern "C" void kernel_launch(void* const* d_in, const int* in_sizes, int n_in,
                              void* d_out, int out_size)
{
    const float* x  = (const float*)d_in[0];
    const float* wl = (const float*)d_in[1];
    const float* wr = (const float*)d_in[2];
    const float* wu = (const float*)d_in[3];
    const float* wd = (const float*)d_in[4];
    float* out = (float*)d_out;

    cudaFuncSetAttribute(rnn_kernel, cudaFuncAttributeMaxDynamicSharedMemorySize, SMEM_BYTES);
    dim3 grid(3072, 4);
    rnn_kernel<<<grid, 256, SMEM_BYTES>>>(x, wl, wr, wu, wd, out);
}

// round 6
// speedup vs baseline: 2.3649x; 2.3649x over previous
#include <cuda_runtime.h>
#include <cuda_fp16.h>
#include <cstdint>

// Spatial RNN, 4 dirs, R=8 steps, C=64. f16 mma.sync + ldmatrix/stmatrix.
// x:(8,192,192,64) fp32; W_*:(64,64); out:(8,192,192,256)
//
// One CTA per scan line (3072 CTAs x 256 thr). Per line: 2 dirs x 8 chained
// [192,64]x[64,64] GEMMs (mma.sync.m16n8k16.f16, f32 accum).
// State: f16 ping-pong smem buffers, 144B row stride (conflict-free LDSM/STSM),
// zero guard rows; the 1-row shift is folded into LDSM row addresses.
// B (weights) live in registers, loaded from L2-hot gmem per direction.

#define STRB 144                 // bytes per buffer row (64 f16 data + pad)
#define BROWS 194                // rows 0..193, guards at 0 and 193
#define BUFB (BROWS * STRB)      // 27936 bytes
#define SMEM_DYN (2 * BUFB + 64) // 55936

static __device__ __forceinline__ uint32_t smem_u32(const void* p) {
    uint32_t a;
    asm("{ .reg .u64 t; cvta.to.shared.u64 t, %1; cvt.u32.u64 %0, t; }" : "=r"(a) : "l"(p));
    return a;
}
static __device__ __forceinline__ uint32_t pkh2(float lo, float hi) {
    uint32_t r;
    asm("cvt.rn.f16x2.f32 %0, %1, %2;" : "=r"(r) : "f"(hi), "f"(lo));
    return r;
}
static __device__ __forceinline__ void ldsm4(uint32_t a[4], uint32_t addr) {
    asm volatile("ldmatrix.sync.aligned.m8n8.x4.shared.b16 {%0,%1,%2,%3}, [%4];"
                 : "=r"(a[0]), "=r"(a[1]), "=r"(a[2]), "=r"(a[3]) : "r"(addr));
}
static __device__ __forceinline__ void stsm4(uint32_t addr, uint32_t r0, uint32_t r1,
                                             uint32_t r2, uint32_t r3) {
    asm volatile("stmatrix.sync.aligned.m8n8.x4.shared.b16 [%0], {%1,%2,%3,%4};"
                 :: "r"(addr), "r"(r0), "r"(r1), "r"(r2), "r"(r3) : "memory");
}
static __device__ __forceinline__ void mma16816(float c[4], const uint32_t a[4],
                                                const uint32_t b[2]) {
    asm volatile(
        "mma.sync.aligned.m16n8k16.row.col.f32.f16.f16.f32 "
        "{%0,%1,%2,%3}, {%4,%5,%6,%7}, {%8,%9}, {%0,%1,%2,%3};"
        : "+f"(c[0]), "+f"(c[1]), "+f"(c[2]), "+f"(c[3])
        : "r"(a[0]), "r"(a[1]), "r"(a[2]), "r"(a[3]), "r"(b[0]), "r"(b[1]));
}
static __device__ __forceinline__ void sts128(uint32_t addr, uint32_t a, uint32_t b,
                                              uint32_t c, uint32_t d) {
    asm volatile("st.shared.v4.b32 [%0], {%1,%2,%3,%4};"
                 :: "r"(addr), "r"(a), "r"(b), "r"(c), "r"(d) : "memory");
}

extern "C" __global__ void __launch_bounds__(256, 1)
rnn_kernel(const float* __restrict__ x,
           const float* __restrict__ W_left, const float* __restrict__ W_right,
           const float* __restrict__ W_up,   const float* __restrict__ W_down,
           float* __restrict__ out)
{
    extern __shared__ char dsm[];
    const uint32_t base = (smem_u32(dsm) + 15u) & ~15u;
    const uint32_t P0 = base;
    const uint32_t P1 = base + BUFB;

    const int tid  = threadIdx.x;
    const int lane = tid & 31;
    const int warp = tid >> 5;
    const int mg   = warp & 3;        // 4 m-groups of 48 rows
    const int ng   = warp >> 2;       // 2 n-groups of 32 cols
    const int gID  = lane >> 2;
    const int tg   = lane & 3;
    const int m0   = mg * 48;
    const int n0   = ng * 32;

    // --- geometry ---
    long inBase, outBase;
    int pixIn, pixOut, chBase;
    const float *Wfp, *Wbp;
    {
        int l = blockIdx.x;
        if (l < 1536) {                            // horizontal row
            inBase  = (long)l * (192 * 64);
            outBase = (long)l * (192 * 256);
            pixIn = 64;  pixOut = 256;  chBase = 0;
            Wfp = W_left;  Wbp = W_right;
        } else {                                    // vertical column
            int l2 = l - 1536;
            int b = l2 / 192, w = l2 % 192;
            inBase  = (long)b * (192 * 192 * 64)  + (long)w * 64;
            outBase = (long)b * (192 * 192 * 256) + (long)w * 256;
            pixIn = 192 * 64;  pixOut = 192 * 256;  chBase = 128;
            Wfp = W_up;  Wbp = W_down;
        }
    }
    const float* xl = x + inBase;
    float* ol = out + outBase;

    // --- zero guard rows (rows 0 and 193; step stores never touch them) ---
    if (tid < 36) {
        asm volatile("st.shared.b32 [%0], %1;" :: "r"(P0 + tid * 4), "r"(0) : "memory");
        asm volatile("st.shared.b32 [%0], %1;" :: "r"(P0 + 193 * STRB + tid * 4), "r"(0) : "memory");
        asm volatile("st.shared.b32 [%0], %1;" :: "r"(P1 + tid * 4), "r"(0) : "memory");
        asm volatile("st.shared.b32 [%0], %1;" :: "r"(P1 + 193 * STRB + tid * 4), "r"(0) : "memory");
    }

    // LDSM/STSM per-thread row/col decomposition:
    //   lanes 0-7 -> mat0 (rows 0-7, colbyte 0), 8-15 -> mat1 (rows 8-15, 0),
    //   16-23 -> mat2 (rows 0-7, colbyte 16), 24-31 -> mat3 (rows 8-15, 16)
    const int lrow = (lane & 7) + ((lane >> 3) & 1) * 8;
    const int lcol = (lane >> 4) * 16;
    const uint32_t stOff = (uint32_t)((m0 + lrow + 1) * STRB + lcol);

    float acc[3][4][4];

    #pragma unroll 1
    for (int dir = 0; dir < 2; dir++) {
        const float* Wg = dir ? Wbp : Wfp;
        const int shift = dir ? 1 : -1;            // fwd reads r-1, bwd reads r+1

        // --- B fragments in registers (f16x2), straight from gmem ---
        uint32_t b[4][4][2];
        #pragma unroll
        for (int kc = 0; kc < 4; kc++)
            #pragma unroll
            for (int nt = 0; nt < 4; nt++) {
                int k0 = kc * 16 + 2 * tg;
                int n  = n0 + nt * 8 + gID;
                b[kc][nt][0] = pkh2(__ldg(&Wg[(k0)     * 64 + n]), __ldg(&Wg[(k0 + 1) * 64 + n]));
                b[kc][nt][1] = pkh2(__ldg(&Wg[(k0 + 8) * 64 + n]), __ldg(&Wg[(k0 + 9) * 64 + n]));
            }

        // --- load x (f16) into P0 rows 1..192 ---
        #pragma unroll
        for (int p = 0; p < 3; p++) {
            int i = tid + p * 256;                  // 0..767
            int r = i >> 2;
            int c0 = (i & 3) * 16;                  // float offset in row
            const float* xp = xl + (long)r * pixIn + c0;
            uint32_t h[8];
            #pragma unroll
            for (int j = 0; j < 4; j++) {
                float4 v = *reinterpret_cast<const float4*>(xp + j * 4);
                h[2 * j]     = pkh2(v.x, v.y);
                h[2 * j + 1] = pkh2(v.z, v.w);
            }
            uint32_t a0 = P0 + (r + 1) * STRB + c0 * 2;
            sts128(a0,      h[0], h[1], h[2], h[3]);
            sts128(a0 + 16, h[4], h[5], h[6], h[7]);
        }

        #pragma unroll
        for (int mt = 0; mt < 3; mt++)
            #pragma unroll
            for (int nt = 0; nt < 4; nt++)
                #pragma unroll
                for (int e = 0; e < 4; e++) acc[mt][nt][e] = 0.f;

        // per-thread LDSM base offset (with shift folded in)
        const uint32_t ldOff = (uint32_t)((m0 + lrow + shift + 1) * STRB + lcol);

        uint32_t src = P0, dst = P1;
        __syncthreads();

        #pragma unroll 1
        for (int s = 0; s < 8; s++) {
            float Cf[3][4][4];
            #pragma unroll
            for (int mt = 0; mt < 3; mt++)
                #pragma unroll
                for (int nt = 0; nt < 4; nt++)
                    #pragma unroll
                    for (int e = 0; e < 4; e++) Cf[mt][nt][e] = 0.f;

            #pragma unroll
            for (int kc = 0; kc < 4; kc++) {
                uint32_t a[3][4];
                #pragma unroll
                for (int mt = 0; mt < 3; mt++)
                    ldsm4(a[mt], src + ldOff + mt * (16 * STRB) + kc * 32);
                #pragma unroll
                for (int mt = 0; mt < 3; mt++)
                    #pragma unroll
                    for (int nt = 0; nt < 4; nt++)
                        mma16816(Cf[mt][nt], a[mt], b[kc][nt]);
            }

            const bool last = (s == 7);
            #pragma unroll
            for (int mt = 0; mt < 3; mt++) {
                uint32_t h[4][2];
                #pragma unroll
                for (int nt = 0; nt < 4; nt++) {
                    float v0 = fmaxf(Cf[mt][nt][0], 0.f);
                    float v1 = fmaxf(Cf[mt][nt][1], 0.f);
                    float v2 = fmaxf(Cf[mt][nt][2], 0.f);
                    float v3 = fmaxf(Cf[mt][nt][3], 0.f);
                    acc[mt][nt][0] += v0;  acc[mt][nt][1] += v1;
                    acc[mt][nt][2] += v2;  acc[mt][nt][3] += v3;
                    h[nt][0] = pkh2(v0, v1);
                    h[nt][1] = pkh2(v2, v3);
                }
                if (!last) {
                    uint32_t sa = dst + stOff + mt * (16 * STRB) + n0 * 2;
                    stsm4(sa,      h[0][0], h[0][1], h[1][0], h[1][1]);
                    stsm4(sa + 32, h[2][0], h[2][1], h[3][0], h[3][1]);
                }
            }

            if (!last) __syncthreads();
            uint32_t t = src; src = dst; dst = t;
        }

        // --- epilogue: out = x + acc ---
        const int cb = chBase + dir * 64;
        #pragma unroll
        for (int mt = 0; mt < 3; mt++) {
            #pragma unroll
            for (int hh = 0; hh < 2; hh++) {
                int gr = m0 + mt * 16 + gID + hh * 8;
                const float* xp = xl + (long)gr * pixIn;
                float* op = ol + (long)gr * pixOut + cb;
                #pragma unroll
                for (int nt = 0; nt < 4; nt++) {
                    int col = n0 + nt * 8 + 2 * tg;
                    float2 xv = *reinterpret_cast<const float2*>(xp + col);
                    float2 o = make_float2(xv.x + acc[mt][nt][2 * hh],
                                           xv.y + acc[mt][nt][2 * hh + 1]);
                    *reinterpret_cast<float2*>(op + col) = o;
                }
            }
        }
        __syncthreads();   // dir-0 smem reads done before dir-1 x-load reuses P0
    }
}

extern "C" void kernel_launch(void* const* d_in, const int* in_sizes, int n_in,
                              void* d_out, int out_size)
{
    const float* x  = (const float*)d_in[0];
    const float* wl = (const float*)d_in[1];
    const float* wr = (const float*)d_in[2];
    const float* wu = (const float*)d_in[3];
    const float* wd = (const float*)d_in[4];
    float* out = (float*)d_out;

    cudaFuncSetAttribute(rnn_kernel, cudaFuncAttributeMaxDynamicSharedMemorySize, SMEM_DYN);
    rnn_kernel<<<3072, 256, SMEM_DYN>>>(x, wl, wr, wu, wd, out);
}